// round 5
// baseline (speedup 1.0000x reference)
#include <cuda_runtime.h>
#include <cuda_bf16.h>

// QuantumConv2d on GB300.
//
// Per 2x2 patch (x0,x1,x2,x3):
//   t_k = sum_q (+-)x_q  (sign = bit q of k, LSB-first)
//   phase_k = -(0.5 t_k + 0.25 t_k^2)   [global-phase term 0.25*sum x^2 dropped]
//   d_k = exp(i phase_k)
//   y = U d, U = RX(w3)(x)RX(w2)(x)RX(w1)(x)RX(w0)  -> group convolution over Z2^4:
//       y = WHT( uhat .* WHT(d) ) / 16,  uhat_s = exp(i/2 sum_q (2 s_q - 1) w_q)
//   state_{F(j)} = 0.25 * y_j, F = CNOT-ring (b1^=b0; b2^=b1'; b3^=b2'; b0^=b3')
//   out_q = sum_j |state|^2 over j where bit (3-q) of F(j) is set.
// 1/64 amplitude scale folded into uhat.
//
// F re-derived (round-3 bug: F[14],F[15] were swapped):
//   F = {0,14,15,1,13,3,2,12,9,7,6,8,4,10,11,5}

// packed f32x2 helpers (FFMA2/FADD2 — PTX-only path on sm_103a)
#define PK2(d, lo, hi)   asm("mov.b64 %0, {%1, %2};" : "=l"(d) : "f"(lo), "f"(hi))
#define UPK2(lo, hi, d)  asm("mov.b64 {%0, %1}, %2;" : "=f"(lo), "=f"(hi) : "l"(d))
#define ADD2(d, a, b)    asm("add.rn.f32x2 %0, %1, %2;" : "=l"(d) : "l"(a), "l"(b))
#define FMA2(d, a, b, c) asm("fma.rn.f32x2 %0, %1, %2, %3;" : "=l"(d) : "l"(a), "l"(b), "l"(c))

__device__ float2 g_uhat[16];

__global__ void uhat_setup_kernel(const float* __restrict__ w) {
    int s = threadIdx.x;
    if (s < 16) {
        float th = 0.0f;
        #pragma unroll
        for (int q = 0; q < 4; q++)
            th += ((s >> q) & 1) ? w[q] : -w[q];
        th *= 0.5f;
        float sn, cs;
        sincosf(th, &sn, &cs);
        g_uhat[s] = make_float2(cs * 0.015625f, sn * 0.015625f);  // 1/64 folded in
    }
}

__global__ __launch_bounds__(256) void qconv_kernel(const float* __restrict__ x,
                                                    float4* __restrict__ out) {
    __shared__ float2 suh[16];
    if (threadIdx.x < 16) suh[threadIdx.x] = g_uhat[threadIdx.x];
    __syncthreads();

    int tid = blockIdx.x * blockDim.x + threadIdx.x;   // = b*16384 + jj*128 + ii
    int b  = tid >> 14;
    int jj = (tid >> 7) & 127;
    int ii = tid & 127;

    // this thread's patch: x[b, 2jj, 2ii..2ii+1], x[b, 2jj+1, 2ii..2ii+1]
    // (self-consistent with writing out[tid]; verified against _PERM + swapaxes)
    const float* p = x + (b << 16) + (jj << 9) + (ii << 1);
    float2 a01 = *(const float2*)(p);
    float2 a23 = *(const float2*)(p + 256);
    float x0 = a01.x, x1 = a01.y, x2 = a23.x, x3 = a23.y;

    // t_k = A[k&3] + B[k>>2]; sign + iff bit set (LSB-first)
    float A[4] = {-x0 - x1,  x0 - x1, -x0 + x1,  x0 + x1};
    float B[4] = {-x2 - x3,  x2 - x3, -x2 + x3,  x2 + x3};

    const unsigned long long NEG1 = 0xBF800000BF800000ULL;  // (-1.f, -1.f)

    unsigned long long v[16];   // packed (re, im)
    #pragma unroll
    for (int k = 0; k < 16; k++) {
        float t  = A[k & 3] + B[k >> 2];
        float ph = t * fmaf(-0.25f, t, -0.5f);   // -(0.5 t + 0.25 t^2)
        float sn, cs;
        __sincosf(ph, &sn, &cs);
        PK2(v[k], cs, sn);
    }

    // WHT #1 on packed complex values
    #pragma unroll
    for (int m = 1; m < 16; m <<= 1) {
        #pragma unroll
        for (int k = 0; k < 16; k++) {
            if (!(k & m)) {
                unsigned long long a = v[k], bb = v[k | m], s, d;
                ADD2(s, a, bb);
                FMA2(d, bb, NEG1, a);
                v[k] = s; v[k | m] = d;
            }
        }
    }

    // pointwise complex multiply by uhat (unit phase, scale folded in)
    #pragma unroll
    for (int s = 0; s < 16; s++) {
        float ur = suh[s].x, ui = suh[s].y;
        float re, im;
        UPK2(re, im, v[s]);
        float r = fmaf(ur, re, -ui * im);
        float i = fmaf(ur, im,  ui * re);
        PK2(v[s], r, i);
    }

    // WHT #2
    #pragma unroll
    for (int m = 1; m < 16; m <<= 1) {
        #pragma unroll
        for (int k = 0; k < 16; k++) {
            if (!(k & m)) {
                unsigned long long a = v[k], bb = v[k | m], s, d;
                ADD2(s, a, bb);
                FMA2(d, bb, NEG1, a);
                v[k] = s; v[k | m] = d;
            }
        }
    }

    // |.|^2, accumulate through CNOT-ring permutation F into per-qubit sums
    const int F[16] = {0, 14, 15, 1, 13, 3, 2, 12, 9, 7, 6, 8, 4, 10, 11, 5};
    float o0 = 0.f, o1 = 0.f, o2 = 0.f, o3 = 0.f;
    #pragma unroll
    for (int j = 0; j < 16; j++) {
        float re, im;
        UPK2(re, im, v[j]);
        float pj = fmaf(re, re, im * im);
        int g = F[j];
        if (g & 8) o0 += pj;   // out_q <- bit (3-q) of F(j)
        if (g & 4) o1 += pj;
        if (g & 2) o2 += pj;
        if (g & 1) o3 += pj;
    }

    out[tid] = make_float4(o0, o1, o2, o3);
}

extern "C" void kernel_launch(void* const* d_in, const int* in_sizes, int n_in,
                              void* d_out, int out_size) {
    const float* x = (const float*)d_in[0];
    const float* w = (const float*)d_in[1];
    if (n_in >= 2 && in_sizes[0] == 4) {   // robustness if metadata order differs
        x = (const float*)d_in[1];
        w = (const float*)d_in[0];
    }
    uhat_setup_kernel<<<1, 16>>>(w);
    qconv_kernel<<<4096, 256>>>(x, (float4*)d_out);
}